// round 1
// baseline (speedup 1.0000x reference)
#include <cuda_runtime.h>
#include <cstdint>
#include <cstddef>

#define N_NODES 200000
#define N_EV    100000
#define D_      128
#define M_      512

// ---------------- scratch (device globals; no allocation in kernel_launch) ---
__device__ unsigned long long g_best[N_NODES];
__device__ int                g_active[N_NODES];
__device__ int                g_count;
__device__ float              g_msg[(size_t)N_NODES * M_];   // [A, 512] compacted messages

// ---------------- helpers ----------------------------------------------------
__device__ __forceinline__ float accurate_cosf(float x) {
    // Cody-Waite range reduction so that fast-math __cosf (if enabled) stays
    // accurate for |x| up to ~1e4. 2*pi = PI2_HI + PI2_LO, PI2_HI has few
    // mantissa bits so k*PI2_HI is exact for |k| < 2^15.
    const float INV2PI = 0.15915493667125702f;
    const float PI2_HI = 6.28125f;
    const float PI2_LO = 1.9353071795864769e-3f;
    float k = rintf(x * INV2PI);
    float r = fmaf(-k, PI2_HI, x);
    r = fmaf(-k, PI2_LO, r);
    return cosf(r);
}

__device__ __forceinline__ float sigmoidf_(float x) {
    return 1.0f / (1.0f + expf(-x));
}

__device__ __forceinline__ void fma2(unsigned long long& d,
                                     unsigned long long a,
                                     unsigned long long b) {
    asm("fma.rn.f32x2 %0, %1, %2, %0;" : "+l"(d) : "l"(a), "l"(b));
}
__device__ __forceinline__ unsigned long long pk(float x) {
    unsigned long long r;
    asm("mov.b64 %0, {%1, %1};" : "=l"(r) : "f"(x));
    return r;
}
__device__ __forceinline__ float lo32(unsigned long long v) {
    return __uint_as_float((unsigned)(v & 0xffffffffu));
}
__device__ __forceinline__ float hi32(unsigned long long v) {
    return __uint_as_float((unsigned)(v >> 32));
}

// ---------------- K1: defaults + init ----------------------------------------
__global__ void k_init(const float* __restrict__ memory,
                       const float* __restrict__ last_update,
                       float* __restrict__ out_mem,
                       float* __restrict__ out_lu) {
    int i = blockIdx.x * blockDim.x + threadIdx.x;
    // copy memory -> out_mem (float4), N*D/4 = 6.4M elements
    const float4* m4 = (const float4*)memory;
    float4* o4 = (float4*)out_mem;
    if (i < N_NODES * D_ / 4) o4[i] = m4[i];
    if (i < N_NODES) {
        if (out_lu) out_lu[i] = last_update[i];
        g_best[i] = 0ULL;
    }
    if (i == 0) g_count = 0;
}

// ---------------- K2: scatter argmax over (t, idx) ---------------------------
__global__ void k_scatter(const int* __restrict__ src,
                          const int* __restrict__ dst,
                          const float* __restrict__ t) {
    int i = blockIdx.x * blockDim.x + threadIdx.x;
    if (i >= 2 * N_EV) return;
    int e = (i < N_EV) ? i : i - N_EV;
    int node = (i < N_EV) ? src[e] : dst[e];
    // t >= 0 so the raw float bit pattern orders like the float value.
    unsigned long long key =
        (((unsigned long long)__float_as_uint(t[e])) << 32) | (unsigned)(i + 1);
    atomicMax(&g_best[node], key);
}

// ---------------- K3: compact + materialize messages -------------------------
__global__ void k_build(const int* __restrict__ src,
                        const int* __restrict__ dst,
                        const float* __restrict__ t,
                        const float* __restrict__ memory,
                        const float* __restrict__ last_update,
                        const float* __restrict__ feat,
                        const float* __restrict__ time_w,
                        const float* __restrict__ time_b,
                        float* __restrict__ out_lu) {
    int node = blockIdx.x;
    unsigned long long key = g_best[node];
    if (key == 0ULL) return;

    __shared__ int s_row;
    int tid = threadIdx.x;
    if (tid == 0) s_row = atomicAdd(&g_count, 1);
    __syncthreads();
    int row = s_row;

    int idx = (int)(key & 0xffffffffu) - 1;
    int e = (idx < N_EV) ? idx : idx - N_EV;
    int other = (idx < N_EV) ? dst[e] : src[e];
    float tt = t[e];
    float dt = tt - last_update[node];

    float* mrow = &g_msg[(size_t)row * M_];
    mrow[tid]          = memory[(size_t)node  * D_ + tid];   // == h
    mrow[D_ + tid]     = memory[(size_t)other * D_ + tid];
    mrow[2 * D_ + tid] = accurate_cosf(fmaf(dt, time_w[tid], time_b[tid]));
    mrow[3 * D_ + tid] = feat[(size_t)e * D_ + tid];

    if (tid == 0) {
        g_active[row] = node;
        if (out_lu) out_lu[node] = tt;
    }
}

// ---------------- K4: fused GEMM + GRU epilogue -------------------------------
// Block tile: 128 nodes x 32 output columns x 3 gates. 128 threads.
// Micro-tile per thread: 8 nodes (4 f32x2 pairs) x 4 contiguous cols.
// Stages 0..15: K=512 against w_ih (accumulate Sr, Sz, In).
// Stages 16..19: K=128 against w_hh, A-tile = msg[:,0:128] == h (Sr, Sz, Hn).
#define BM 128
#define BK 32
#define BC 32

#define INNER_K(kk, ACC3) do {                                                 \
    unsigned long long a2_[4];                                                  \
    _Pragma("unroll")                                                           \
    for (int i_ = 0; i_ < 4; i_++)                                              \
        a2_[i_] = *(const unsigned long long*)&As[kk][m0 + 2 * i_];             \
    _Pragma("unroll")                                                           \
    for (int j_ = 0; j_ < 4; j_++) {                                            \
        unsigned long long br_ = pk(Bs[0][c0 + j_][kk]);                        \
        unsigned long long bz_ = pk(Bs[1][c0 + j_][kk]);                        \
        unsigned long long bn_ = pk(Bs[2][c0 + j_][kk]);                        \
        _Pragma("unroll")                                                       \
        for (int i_ = 0; i_ < 4; i_++) {                                        \
            fma2(sr2[i_][j_], a2_[i_], br_);                                    \
            fma2(sz2[i_][j_], a2_[i_], bz_);                                    \
            fma2(ACC3[i_][j_], a2_[i_], bn_);                                   \
        }                                                                       \
    }                                                                           \
} while (0)

__global__ void __launch_bounds__(128)
k_gru(const float* __restrict__ w_ih, const float* __restrict__ w_hh,
      const float* __restrict__ b_ih, const float* __restrict__ b_hh,
      float* __restrict__ out_mem) {
    const int A = g_count;
    const int mbase = blockIdx.x * BM;
    if (mbase >= A) return;
    const int cbase = blockIdx.y * BC;          // 0,32,64,96

    __shared__ __align__(16) float As[BK][BM + 2];      // [k][m], pad 2 keeps f32x2 aligned
    __shared__ __align__(16) float Bs[3][BC][BK + 1];   // [gate][c][k], pad 1 avoids conflicts
    __shared__ int ns[BM];

    const int tid = threadIdx.x;
    const int ty = tid >> 3;            // 0..15
    const int tx = tid & 7;             // 0..7
    const int m0 = ty * 8;              // 8 nodes per thread
    const int c0 = tx * 4;              // 4 contiguous cols per thread

    {
        int m = mbase + tid;
        ns[tid] = g_active[(m < A) ? m : 0];
    }

    unsigned long long sr2[4][4], sz2[4][4], in2[4][4], hn2[4][4];
#pragma unroll
    for (int i = 0; i < 4; i++)
#pragma unroll
        for (int j = 0; j < 4; j++) {
            sr2[i][j] = 0ULL; sz2[i][j] = 0ULL; in2[i][j] = 0ULL; hn2[i][j] = 0ULL;
        }

    const int mrow_src = (mbase + tid < A) ? (mbase + tid) : 0;
    const float* gsrc_base = &g_msg[(size_t)mrow_src * M_];

    for (int s = 0; s < 20; ++s) {
        const bool ph2 = (s >= 16);
        const float* W = ph2 ? w_hh : w_ih;
        const int Kdim = ph2 ? D_ : M_;
        const int koff = ph2 ? (s - 16) * BK : s * BK;

        __syncthreads();
        // A tile: thread tid owns node row tid; transpose into [k][m]
        {
            const float* gsrc = gsrc_base + koff;   // h-phase reads msg cols 0..127 = h
#pragma unroll
            for (int k4 = 0; k4 < BK; k4 += 4) {
                float4 v = *(const float4*)(gsrc + k4);
                As[k4 + 0][tid] = v.x;
                As[k4 + 1][tid] = v.y;
                As[k4 + 2][tid] = v.z;
                As[k4 + 3][tid] = v.w;
            }
        }
        // B tiles: 3 gates x 32 rows x 32 k
        {
            int c  = tid >> 2;           // 0..31
            int kq = (tid & 3) * 8;      // 0,8,16,24
#pragma unroll
            for (int g = 0; g < 3; g++) {
                const float* wsrc = &W[(size_t)(g * D_ + cbase + c) * Kdim + koff + kq];
                float4 v0 = *(const float4*)(wsrc);
                float4 v1 = *(const float4*)(wsrc + 4);
                Bs[g][c][kq + 0] = v0.x; Bs[g][c][kq + 1] = v0.y;
                Bs[g][c][kq + 2] = v0.z; Bs[g][c][kq + 3] = v0.w;
                Bs[g][c][kq + 4] = v1.x; Bs[g][c][kq + 5] = v1.y;
                Bs[g][c][kq + 6] = v1.z; Bs[g][c][kq + 7] = v1.w;
            }
        }
        __syncthreads();

        if (!ph2) {
#pragma unroll 8
            for (int kk = 0; kk < BK; kk++) INNER_K(kk, in2);
        } else {
#pragma unroll 8
            for (int kk = 0; kk < BK; kk++) INNER_K(kk, hn2);
        }
    }

    // ---- epilogue: gates + blend + scatter ----
    float bsum_r[4], bsum_z[4], bi_n[4], bh_n[4];
#pragma unroll
    for (int j = 0; j < 4; j++) {
        int jg = cbase + c0 + j;
        bsum_r[j] = b_ih[jg] + b_hh[jg];
        bsum_z[j] = b_ih[D_ + jg] + b_hh[D_ + jg];
        bi_n[j]   = b_ih[2 * D_ + jg];
        bh_n[j]   = b_hh[2 * D_ + jg];
    }

#pragma unroll
    for (int i = 0; i < 4; i++) {
#pragma unroll
        for (int h2 = 0; h2 < 2; h2++) {
            int mm = m0 + 2 * i + h2;
            int m = mbase + mm;
            if (m >= A) continue;
            int node = ns[mm];
            float4 hv = *(const float4*)&g_msg[(size_t)m * M_ + cbase + c0];
            const float* hvp = &hv.x;
            float res[4];
#pragma unroll
            for (int j = 0; j < 4; j++) {
                float srv = h2 ? hi32(sr2[i][j]) : lo32(sr2[i][j]);
                float szv = h2 ? hi32(sz2[i][j]) : lo32(sz2[i][j]);
                float inv = h2 ? hi32(in2[i][j]) : lo32(in2[i][j]);
                float hnv = h2 ? hi32(hn2[i][j]) : lo32(hn2[i][j]);
                float r = sigmoidf_(srv + bsum_r[j]);
                float z = sigmoidf_(szv + bsum_z[j]);
                float nn = tanhf(inv + bi_n[j] + r * (hnv + bh_n[j]));
                res[j] = (1.0f - z) * nn + z * hvp[j];
            }
            *(float4*)&out_mem[(size_t)node * D_ + cbase + c0] =
                make_float4(res[0], res[1], res[2], res[3]);
        }
    }
}

// ---------------- launch ------------------------------------------------------
extern "C" void kernel_launch(void* const* d_in, const int* in_sizes, int n_in,
                              void* d_out, int out_size) {
    const float* memory      = (const float*)d_in[0];
    const float* last_update = (const float*)d_in[1];
    const float* t           = (const float*)d_in[2];
    const float* feat        = (const float*)d_in[3];
    const float* time_w      = (const float*)d_in[4];
    const float* time_b      = (const float*)d_in[5];
    const float* w_ih        = (const float*)d_in[6];
    const float* w_hh        = (const float*)d_in[7];
    const float* b_ih        = (const float*)d_in[8];
    const float* b_hh        = (const float*)d_in[9];
    const int*   src         = (const int*)d_in[10];
    const int*   dst         = (const int*)d_in[11];

    float* out_mem = (float*)d_out;
    float* out_lu  = (out_size >= N_NODES * D_ + N_NODES)
                         ? out_mem + (size_t)N_NODES * D_ : nullptr;

    k_init<<<(N_NODES * D_ / 4 + 255) / 256, 256>>>(memory, last_update, out_mem, out_lu);
    k_scatter<<<(2 * N_EV + 255) / 256, 256>>>(src, dst, t);
    k_build<<<N_NODES, 128>>>(src, dst, t, memory, last_update, feat,
                              time_w, time_b, out_lu);
    dim3 grid((N_NODES + BM - 1) / BM, D_ / BC);
    k_gru<<<grid, 128>>>(w_ih, w_hh, b_ih, b_hh, out_mem);
}

// round 3
// speedup vs baseline: 2.3712x; 2.3712x over previous
#include <cuda_runtime.h>
#include <cuda_bf16.h>
#include <cstdint>
#include <cstddef>

#define N_NODES 200000
#define N_EV    100000
#define D_      128
#define PADM    200064          // N_NODES rounded up to 128
#define NCHUNK  20              // K chunks of 32 fp32
#define ROWBF   1280            // bf16 elems per packed row
#define ROWBYTES 2560           // bytes per packed row

// ---------------- scratch (device globals) -----------------------------------
__device__ unsigned long long g_best[N_NODES];
__device__ int                g_active[N_NODES];
__device__ int                g_count;
__device__ __align__(16) __nv_bfloat16 g_msg[(size_t)PADM * ROWBF];
__device__ __align__(16) __nv_bfloat16 g_w[(size_t)384 * ROWBF];
__device__ float              g_out[(size_t)4 * PADM * 128];  // r | z | n_i | n_h

// ---------------- helpers -----------------------------------------------------
__device__ __forceinline__ uint32_t smem_u32(const void* p) {
    uint32_t a;
    asm("{ .reg .u64 t; cvta.to.shared.u64 t, %1; cvt.u32.u64 %0, t; }"
        : "=r"(a) : "l"(p));
    return a;
}
__device__ __forceinline__ void cp16(uint32_t dst, const void* src) {
    asm volatile("cp.async.cg.shared.global [%0], [%1], 16;" :: "r"(dst), "l"(src));
}
__device__ __forceinline__ uint32_t lds32(uint32_t addr) {
    uint32_t v;
    asm volatile("ld.shared.b32 %0, [%1];" : "=r"(v) : "r"(addr));
    return v;
}
// swizzled byte offset of element (row r, byte-in-row kb<64) in a 128x64B tile
__device__ __forceinline__ int swz(int r, int kb) {
    return r * 64 + ((((kb >> 4) ^ ((r >> 1) & 3)) << 4) | (kb & 15));
}
__device__ __forceinline__ void mma16816(float* d, const uint32_t* a, const uint32_t* b) {
    asm volatile("mma.sync.aligned.m16n8k16.row.col.f32.bf16.bf16.f32 "
        "{%0,%1,%2,%3}, {%4,%5,%6,%7}, {%8,%9}, {%0,%1,%2,%3};"
        : "+f"(d[0]), "+f"(d[1]), "+f"(d[2]), "+f"(d[3])
        : "r"(a[0]), "r"(a[1]), "r"(a[2]), "r"(a[3]), "r"(b[0]), "r"(b[1]));
}

__device__ __forceinline__ float accurate_cosf(float x) {
    const float INV2PI = 0.15915493667125702f;
    const float PI2_HI = 6.28125f;
    const float PI2_LO = 1.9353071795864769e-3f;
    float k = rintf(x * INV2PI);
    float r = fmaf(-k, PI2_HI, x);
    r = fmaf(-k, PI2_LO, r);
    return cosf(r);
}
__device__ __forceinline__ float sigmoidf_(float x) { return 1.0f / (1.0f + expf(-x)); }

__device__ __forceinline__ void store_hilo(__nv_bfloat16* row, int c, float v) {
    int ch = c >> 5, pos = c & 31;
    __nv_bfloat16 h = __float2bfloat16(v);
    __nv_bfloat16 l = __float2bfloat16(v - __bfloat162float(h));
    row[ch * 64 + pos]      = h;
    row[ch * 64 + 32 + pos] = l;
}

// ---------------- K1: defaults + init ------------------------------------------
__global__ void k_init(const float* __restrict__ memory,
                       const float* __restrict__ last_update,
                       float* __restrict__ out_mem,
                       float* __restrict__ out_lu) {
    int i = blockIdx.x * blockDim.x + threadIdx.x;
    const float4* m4 = (const float4*)memory;
    float4* o4 = (float4*)out_mem;
    if (i < N_NODES * D_ / 4) o4[i] = m4[i];
    if (i < N_NODES) {
        if (out_lu) out_lu[i] = last_update[i];
        g_best[i] = 0ULL;
    }
    if (i == 0) g_count = 0;
}

// ---------------- K2: scatter argmax --------------------------------------------
__global__ void k_scatter(const int* __restrict__ src,
                          const int* __restrict__ dst,
                          const float* __restrict__ t) {
    int i = blockIdx.x * blockDim.x + threadIdx.x;
    if (i >= 2 * N_EV) return;
    int e = (i < N_EV) ? i : i - N_EV;
    int node = (i < N_EV) ? src[e] : dst[e];
    unsigned long long key =
        (((unsigned long long)__float_as_uint(t[e])) << 32) | (unsigned)(i + 1);
    atomicMax(&g_best[node], key);
}

// ---------------- K3: compact + build packed bf16 messages ----------------------
__global__ void k_build(const int* __restrict__ src,
                        const int* __restrict__ dst,
                        const float* __restrict__ t,
                        const float* __restrict__ memory,
                        const float* __restrict__ last_update,
                        const float* __restrict__ feat,
                        const float* __restrict__ time_w,
                        const float* __restrict__ time_b,
                        float* __restrict__ out_lu) {
    int node = blockIdx.x;
    unsigned long long key = g_best[node];
    if (key == 0ULL) return;

    __shared__ int s_row;
    int tid = threadIdx.x;
    if (tid == 0) s_row = atomicAdd(&g_count, 1);
    __syncthreads();
    int row = s_row;

    int idx = (int)(key & 0xffffffffu) - 1;
    int e = (idx < N_EV) ? idx : idx - N_EV;
    int other = (idx < N_EV) ? dst[e] : src[e];
    float tt = t[e];
    float dt = tt - last_update[node];

    __nv_bfloat16* mrow = g_msg + (size_t)row * ROWBF;
    float v0 = memory[(size_t)node * D_ + tid];
    float v1 = memory[(size_t)other * D_ + tid];
    float v2 = accurate_cosf(fmaf(dt, time_w[tid], time_b[tid]));
    float v3 = feat[(size_t)e * D_ + tid];
    store_hilo(mrow, tid, v0);
    store_hilo(mrow, 128 + tid, v1);
    store_hilo(mrow, 256 + tid, v2);
    store_hilo(mrow, 384 + tid, v3);
    store_hilo(mrow, 512 + tid, v0);   // h duplicated for the w_hh K range

    if (tid == 0) {
        g_active[row] = node;
        if (out_lu) out_lu[node] = tt;
    }
}

// ---------------- K4: prepack weights -------------------------------------------
__global__ void k_packw(const float* __restrict__ w_ih,
                        const float* __restrict__ w_hh) {
    int n = blockIdx.x;
    int tid = threadIdx.x;
    __nv_bfloat16* row = g_w + (size_t)n * ROWBF;
    const float* wi = w_ih + (size_t)n * 512;
#pragma unroll
    for (int s = 0; s < 4; s++) store_hilo(row, s * 128 + tid, wi[s * 128 + tid]);
    store_hilo(row, 512 + tid, w_hh[(size_t)n * 128 + tid]);
}

// ---------------- K5: split-bf16 mma.sync GEMM ----------------------------------
// grid = (ceil(N/128), 4). gy: 0=r, 1=z (chunks 0..19), 2=n_i (0..15), 3=n_h (16..19)
// Stage (32KB): A_hi 8K | A_lo 8K | B_hi 8K | B_lo 8K. Double buffered (64KB).
#define STAGE 32768

__global__ void __launch_bounds__(256, 2)
k_gemm() {
    extern __shared__ char smdyn[];
    const int A = g_count;
    const int mbase = blockIdx.x * 128;
    if (mbase >= A) return;
    const int gy = blockIdx.y;
    const int cfirst  = (gy == 3) ? 16 : 0;
    const int nchunks = (gy == 2) ? 16 : ((gy == 3) ? 4 : 20);
    const int wrow = (gy >= 2) ? 256 : gy * 128;

    const int tid = threadIdx.x;
    const int wid = tid >> 5, lane = tid & 31;
    const int g = lane >> 2, t4 = (lane & 3) * 4;
    const int m0 = (wid >> 1) * 32, n0 = (wid & 1) * 64;

    const uint32_t smb = smem_u32(smdyn);
    const char* abase = (const char*)g_msg + (size_t)mbase * ROWBYTES;
    const char* bbase = (const char*)g_w + (size_t)wrow * ROWBYTES;

    auto issue = [&](int ci, int s) {
        int chunk = cfirst + ci;
        uint32_t st = smb + s * STAGE;
#pragma unroll
        for (int i = 0; i < 4; i++) {
            int idx = tid + 256 * i;
            int r = idx >> 3, q = idx & 7;
            uint32_t dst = st + (q >> 2) * 8192 + r * 64 + (((q & 3) ^ ((r >> 1) & 3)) << 4);
            cp16(dst, abase + (size_t)r * ROWBYTES + chunk * 128 + q * 16);
        }
#pragma unroll
        for (int i = 0; i < 4; i++) {
            int idx = tid + 256 * i;
            int r = idx >> 3, q = idx & 7;
            uint32_t dst = st + 16384 + (q >> 2) * 8192 + r * 64 + (((q & 3) ^ ((r >> 1) & 3)) << 4);
            cp16(dst, bbase + (size_t)r * ROWBYTES + chunk * 128 + q * 16);
        }
        asm volatile("cp.async.commit_group;" ::: "memory");
    };

    float acc[2][8][4];
#pragma unroll
    for (int mi = 0; mi < 2; mi++)
#pragma unroll
        for (int ni = 0; ni < 8; ni++)
#pragma unroll
            for (int j = 0; j < 4; j++) acc[mi][ni][j] = 0.0f;

    issue(0, 0);
    if (nchunks > 1) issue(1, 1);

    for (int ci = 0; ci < nchunks; ci++) {
        int s = ci & 1;
        if (ci + 1 < nchunks)
            asm volatile("cp.async.wait_group 1;" ::: "memory");
        else
            asm volatile("cp.async.wait_group 0;" ::: "memory");
        __syncthreads();

        uint32_t st = smb + s * STAGE;
        uint32_t Ah = st, Al = st + 8192, Bh = st + 16384, Bl = st + 24576;

#pragma unroll
        for (int kk = 0; kk < 2; kk++) {
            int kb = kk * 32 + t4;
            uint32_t ah[2][4], al[2][4];
#pragma unroll
            for (int mi = 0; mi < 2; mi++) {
                int r = m0 + mi * 16 + g;
                ah[mi][0] = lds32(Ah + swz(r,     kb));
                ah[mi][1] = lds32(Ah + swz(r + 8, kb));
                ah[mi][2] = lds32(Ah + swz(r,     kb + 16));
                ah[mi][3] = lds32(Ah + swz(r + 8, kb + 16));
                al[mi][0] = lds32(Al + swz(r,     kb));
                al[mi][1] = lds32(Al + swz(r + 8, kb));
                al[mi][2] = lds32(Al + swz(r,     kb + 16));
                al[mi][3] = lds32(Al + swz(r + 8, kb + 16));
            }
#pragma unroll
            for (int ni = 0; ni < 8; ni++) {
                int br = n0 + ni * 8 + g;
                uint32_t bh[2], bl[2];
                bh[0] = lds32(Bh + swz(br, kb));
                bh[1] = lds32(Bh + swz(br, kb + 16));
                bl[0] = lds32(Bl + swz(br, kb));
                bl[1] = lds32(Bl + swz(br, kb + 16));
#pragma unroll
                for (int mi = 0; mi < 2; mi++) {
                    mma16816(acc[mi][ni], ah[mi], bh);
                    mma16816(acc[mi][ni], ah[mi], bl);
                    mma16816(acc[mi][ni], al[mi], bh);
                }
            }
        }
        __syncthreads();
        if (ci + 2 < nchunks) issue(ci + 2, s);
    }

    float* outr = g_out + (size_t)gy * PADM * 128;
#pragma unroll
    for (int mi = 0; mi < 2; mi++) {
        int row0 = mbase + m0 + mi * 16 + g;
#pragma unroll
        for (int ni = 0; ni < 8; ni++) {
            int col = n0 + ni * 8 + (t4 >> 1);
            *(float2*)&outr[(size_t)row0 * 128 + col] =
                make_float2(acc[mi][ni][0], acc[mi][ni][1]);
            *(float2*)&outr[(size_t)(row0 + 8) * 128 + col] =
                make_float2(acc[mi][ni][2], acc[mi][ni][3]);
        }
    }
}

// ---------------- K6: GRU epilogue ----------------------------------------------
__global__ void k_epi(const float* __restrict__ memory,
                      const float* __restrict__ b_ih,
                      const float* __restrict__ b_hh,
                      float* __restrict__ out_mem) {
    const int A = g_count;
    int i = blockIdx.x * blockDim.x + threadIdx.x;
    int m = i >> 5;
    if (m >= A) return;
    int c = (i & 31) * 4;
    int node = g_active[m];

    const size_t off = (size_t)m * 128 + c;
    const size_t REG = (size_t)PADM * 128;
    float4 vr  = *(const float4*)&g_out[off];
    float4 vz  = *(const float4*)&g_out[REG + off];
    float4 vni = *(const float4*)&g_out[2 * REG + off];
    float4 vnh = *(const float4*)&g_out[3 * REG + off];
    float4 hv  = *(const float4*)&memory[(size_t)node * D_ + c];
    float4 bi_r = *(const float4*)&b_ih[c];
    float4 bh_r = *(const float4*)&b_hh[c];
    float4 bi_z = *(const float4*)&b_ih[128 + c];
    float4 bh_z = *(const float4*)&b_hh[128 + c];
    float4 bi_n = *(const float4*)&b_ih[256 + c];
    float4 bh_n = *(const float4*)&b_hh[256 + c];

    const float* pr = &vr.x;  const float* pz = &vz.x;
    const float* pni = &vni.x; const float* pnh = &vnh.x;
    const float* ph = &hv.x;
    const float* pbir = &bi_r.x; const float* pbhr = &bh_r.x;
    const float* pbiz = &bi_z.x; const float* pbhz = &bh_z.x;
    const float* pbin = &bi_n.x; const float* pbhn = &bh_n.x;

    float res[4];
#pragma unroll
    for (int j = 0; j < 4; j++) {
        float r = sigmoidf_(pr[j] + pbir[j] + pbhr[j]);
        float z = sigmoidf_(pz[j] + pbiz[j] + pbhz[j]);
        float n = tanhf(pni[j] + pbin[j] + r * (pnh[j] + pbhn[j]));
        res[j] = (1.0f - z) * n + z * ph[j];
    }
    *(float4*)&out_mem[(size_t)node * D_ + c] =
        make_float4(res[0], res[1], res[2], res[3]);
}

// ---------------- launch ----------------------------------------------------------
extern "C" void kernel_launch(void* const* d_in, const int* in_sizes, int n_in,
                              void* d_out, int out_size) {
    const float* memory      = (const float*)d_in[0];
    const float* last_update = (const float*)d_in[1];
    const float* t           = (const float*)d_in[2];
    const float* feat        = (const float*)d_in[3];
    const float* time_w      = (const float*)d_in[4];
    const float* time_b      = (const float*)d_in[5];
    const float* w_ih        = (const float*)d_in[6];
    const float* w_hh        = (const float*)d_in[7];
    const float* b_ih        = (const float*)d_in[8];
    const float* b_hh        = (const float*)d_in[9];
    const int*   src         = (const int*)d_in[10];
    const int*   dst         = (const int*)d_in[11];

    float* out_mem = (float*)d_out;
    float* out_lu  = (out_size >= N_NODES * D_ + N_NODES)
                         ? out_mem + (size_t)N_NODES * D_ : nullptr;

    cudaFuncSetAttribute(k_gemm, cudaFuncAttributeMaxDynamicSharedMemorySize,
                         2 * STAGE);

    k_packw<<<384, 128>>>(w_ih, w_hh);
    k_init<<<(N_NODES * D_ / 4 + 255) / 256, 256>>>(memory, last_update, out_mem, out_lu);
    k_scatter<<<(2 * N_EV + 255) / 256, 256>>>(src, dst, t);
    k_build<<<N_NODES, 128>>>(src, dst, t, memory, last_update, feat,
                              time_w, time_b, out_lu);
    dim3 grid((N_NODES + 127) / 128, 4);
    k_gemm<<<grid, 256, 2 * STAGE>>>();
    k_epi<<<(N_NODES * 32 + 255) / 256, 256>>>(memory, b_ih, b_hh, out_mem);
}

// round 4
// speedup vs baseline: 3.5292x; 1.4883x over previous
#include <cuda_runtime.h>
#include <cuda_fp16.h>
#include <cstdint>
#include <cstddef>

#define N_NODES 200000
#define N_EV    100000
#define D_      128
#define PADM    200064          // N_NODES rounded up to 128

// ---------------- scratch (device globals) -----------------------------------
__device__ unsigned long long g_best[N_NODES];
__device__ int                g_active[N_NODES];
__device__ int                g_count;
__device__ __align__(16) __half g_msg[(size_t)PADM * 512];   // fp16 messages
__device__ __align__(16) __half g_wh[(size_t)384 * 640];     // weight hi
__device__ __align__(16) __half g_wl[(size_t)384 * 640];     // weight lo
__device__ __align__(16) __half g_out[(size_t)4 * PADM * 128]; // r|z|n_i|n_h preacts

// ---------------- helpers -----------------------------------------------------
__device__ __forceinline__ uint32_t smem_u32(const void* p) {
    uint32_t a;
    asm("{ .reg .u64 t; cvta.to.shared.u64 t, %1; cvt.u32.u64 %0, t; }"
        : "=r"(a) : "l"(p));
    return a;
}
__device__ __forceinline__ void cp16(uint32_t dst, const void* src) {
    asm volatile("cp.async.cg.shared.global [%0], [%1], 16;" :: "r"(dst), "l"(src));
}
// swizzled byte offset of (row r, byte col c) in a 128-rows x 128B tile
__device__ __forceinline__ uint32_t swz(int r, int c) {
    return (uint32_t)(r * 128 + ((((c >> 4) ^ (r & 7)) << 4) | (c & 15)));
}
__device__ __forceinline__ void ldsm4(uint32_t* r, uint32_t addr) {
    asm volatile("ldmatrix.sync.aligned.m8n8.x4.shared.b16 {%0,%1,%2,%3}, [%4];"
        : "=r"(r[0]), "=r"(r[1]), "=r"(r[2]), "=r"(r[3]) : "r"(addr));
}
__device__ __forceinline__ void mma16816(float* d, const uint32_t* a, const uint32_t* b) {
    asm volatile("mma.sync.aligned.m16n8k16.row.col.f32.f16.f16.f32 "
        "{%0,%1,%2,%3}, {%4,%5,%6,%7}, {%8,%9}, {%0,%1,%2,%3};"
        : "+f"(d[0]), "+f"(d[1]), "+f"(d[2]), "+f"(d[3])
        : "r"(a[0]), "r"(a[1]), "r"(a[2]), "r"(a[3]), "r"(b[0]), "r"(b[1]));
}

__device__ __forceinline__ float accurate_cosf(float x) {
    const float INV2PI = 0.15915493667125702f;
    const float PI2_HI = 6.28125f;
    const float PI2_LO = 1.9353071795864769e-3f;
    float k = rintf(x * INV2PI);
    float r = fmaf(-k, PI2_HI, x);
    r = fmaf(-k, PI2_LO, r);
    return cosf(r);
}
__device__ __forceinline__ float sigmoidf_(float x) { return 1.0f / (1.0f + expf(-x)); }

// ---------------- K0: zero flags ------------------------------------------------
__global__ void k_zero() {
    int i = blockIdx.x * blockDim.x + threadIdx.x;
    if (i < N_NODES) g_best[i] = 0ULL;
    if (i == 0) g_count = 0;
}

// ---------------- K2: scatter argmax --------------------------------------------
__global__ void k_scatter(const int* __restrict__ src,
                          const int* __restrict__ dst,
                          const float* __restrict__ t) {
    int i = blockIdx.x * blockDim.x + threadIdx.x;
    if (i >= 2 * N_EV) return;
    int e = (i < N_EV) ? i : i - N_EV;
    int node = (i < N_EV) ? src[e] : dst[e];
    unsigned long long key =
        (((unsigned long long)__float_as_uint(t[e])) << 32) | (unsigned)(i + 1);
    atomicMax(&g_best[node], key);
}

// ---------------- K1: defaults for inactive nodes (after scatter) ---------------
__global__ void k_init(const float* __restrict__ memory,
                       const float* __restrict__ last_update,
                       float* __restrict__ out_mem,
                       float* __restrict__ out_lu) {
    int i = blockIdx.x * blockDim.x + threadIdx.x;
    if (i < N_NODES * 32) {
        int node = i >> 5;
        if (g_best[node] == 0ULL)
            ((float4*)out_mem)[i] = ((const float4*)memory)[i];
    }
    if (i < N_NODES && out_lu && g_best[i] == 0ULL)
        out_lu[i] = last_update[i];
}

// ---------------- K3: compact + build fp16 messages ------------------------------
__global__ void k_build(const int* __restrict__ src,
                        const int* __restrict__ dst,
                        const float* __restrict__ t,
                        const float* __restrict__ memory,
                        const float* __restrict__ last_update,
                        const float* __restrict__ feat,
                        const float* __restrict__ time_w,
                        const float* __restrict__ time_b,
                        float* __restrict__ out_lu) {
    int node = blockIdx.x;
    unsigned long long key = g_best[node];
    if (key == 0ULL) return;

    __shared__ int s_row;
    int tid = threadIdx.x;
    if (tid == 0) s_row = atomicAdd(&g_count, 1);
    __syncthreads();
    int row = s_row;

    int idx = (int)(key & 0xffffffffu) - 1;
    int e = (idx < N_EV) ? idx : idx - N_EV;
    int other = (idx < N_EV) ? dst[e] : src[e];
    float tt = t[e];
    float dt = tt - last_update[node];

    __half* mrow = g_msg + (size_t)row * 512;
    mrow[tid]       = __float2half_rn(memory[(size_t)node * D_ + tid]);
    mrow[128 + tid] = __float2half_rn(memory[(size_t)other * D_ + tid]);
    mrow[256 + tid] = __float2half_rn(accurate_cosf(fmaf(dt, time_w[tid], time_b[tid])));
    mrow[384 + tid] = __float2half_rn(feat[(size_t)e * D_ + tid]);

    if (tid == 0) {
        g_active[row] = node;
        if (out_lu) out_lu[node] = tt;
    }
}

// ---------------- K4: prepack weights (hi/lo fp16) --------------------------------
// g_wh/g_wl row n (0..383): cols 0..511 = w_ih[n], cols 512..639 = w_hh[n]
__global__ void k_packw(const float* __restrict__ w_ih,
                        const float* __restrict__ w_hh) {
    int n = blockIdx.x;
    int tid = threadIdx.x;
    __half* rh = g_wh + (size_t)n * 640;
    __half* rl = g_wl + (size_t)n * 640;
#pragma unroll
    for (int s = 0; s < 5; s++) {
        int col = s * 128 + tid;
        float w = (s < 4) ? w_ih[(size_t)n * 512 + col]
                          : w_hh[(size_t)n * 128 + tid];
        __half h = __float2half_rn(w);
        rh[col] = h;
        rl[col] = __float2half_rn(w - __half2float(h));
    }
}

// ---------------- K5: fp16 2-term mma.sync GEMM ------------------------------------
// grid = (ceil(N/128), 4). gy: 0=r, 1=z (K=640), 2=n_i (K=512), 3=n_h (K=128).
// Step = 64 K-cols. Stage (48KB): A 16K | Bhi 16K | Blo 16K. Double buffered (96KB).
#define STAGE 49152

__global__ void __launch_bounds__(256, 2)
k_gemm() {
    extern __shared__ char smdyn[];
    const int A = g_count;
    const int mbase = blockIdx.x * 128;
    if (mbase >= A) return;
    const int gy = blockIdx.y;
    const int nsteps = (gy < 2) ? 10 : ((gy == 2) ? 8 : 2);
    const int wrow = (gy >= 2) ? 256 : gy * 128;

    const int tid = threadIdx.x;
    const int wid = tid >> 5, lane = tid & 31;
    const int m0 = (wid >> 1) * 32, n0 = (wid & 1) * 64;
    const uint32_t smb = smem_u32(smdyn);

    const char* bh_mem = (const char*)g_wh + (size_t)wrow * 1280;
    const char* bl_mem = (const char*)g_wl + (size_t)wrow * 1280;
    const char* a_mem = (const char*)g_msg;

    auto issue = [&](int s, int buf) {
        // byte offsets into the 1024B A row / 1280B W row
        int ac = (gy < 2 && s >= 8) ? (s - 8) * 128 : s * 128;
        int wc = (gy == 3) ? 1024 + s * 128
                           : ((gy < 2 && s >= 8) ? 1024 + (s - 8) * 128 : s * 128);
        uint32_t st = smb + buf * STAGE;
#pragma unroll
        for (int i = 0; i < 4; i++) {
            int idx = tid + 256 * i;
            int r = idx >> 3, q = (idx & 7) * 16;
            int gr = mbase + r;
            if (gr >= A) gr = A - 1;
            cp16(st + swz(r, q), a_mem + (size_t)gr * 1024 + ac + q);
        }
#pragma unroll
        for (int i = 0; i < 4; i++) {
            int idx = tid + 256 * i;
            int r = idx >> 3, q = (idx & 7) * 16;
            cp16(st + 16384 + swz(r, q), bh_mem + (size_t)r * 1280 + wc + q);
        }
#pragma unroll
        for (int i = 0; i < 4; i++) {
            int idx = tid + 256 * i;
            int r = idx >> 3, q = (idx & 7) * 16;
            cp16(st + 32768 + swz(r, q), bl_mem + (size_t)r * 1280 + wc + q);
        }
        asm volatile("cp.async.commit_group;" ::: "memory");
    };

    float acc[2][8][4];
#pragma unroll
    for (int mi = 0; mi < 2; mi++)
#pragma unroll
        for (int ni = 0; ni < 8; ni++)
#pragma unroll
            for (int j = 0; j < 4; j++) acc[mi][ni][j] = 0.0f;

    issue(0, 0);
    if (nsteps > 1) issue(1, 1);

    // ldmatrix per-lane address components
    const int arow = lane & 15;
    const int acoll = (lane >> 4) << 4;
    const int browl = (lane & 7) + ((lane & 16) >> 1);
    const int bcoll = (lane & 8) << 1;

    for (int s = 0; s < nsteps; s++) {
        int buf = s & 1;
        if (s + 1 < nsteps)
            asm volatile("cp.async.wait_group 1;" ::: "memory");
        else
            asm volatile("cp.async.wait_group 0;" ::: "memory");
        __syncthreads();

        uint32_t Ast = smb + buf * STAGE;
        uint32_t Bh = Ast + 16384, Bl = Ast + 32768;

#pragma unroll
        for (int kk = 0; kk < 4; kk++) {
            int kb = kk * 32;
            uint32_t a[2][4];
            ldsm4(a[0], Ast + swz(m0 + arow, kb + acoll));
            ldsm4(a[1], Ast + swz(m0 + 16 + arow, kb + acoll));
#pragma unroll
            for (int np = 0; np < 4; np++) {
                int nb = n0 + np * 16 + browl;
                uint32_t bhf[4], blf[4];
                ldsm4(bhf, Bh + swz(nb, kb + bcoll));
                ldsm4(blf, Bl + swz(nb, kb + bcoll));
#pragma unroll
                for (int mi = 0; mi < 2; mi++) {
                    mma16816(acc[mi][np * 2],     a[mi], bhf);
                    mma16816(acc[mi][np * 2],     a[mi], blf);
                    mma16816(acc[mi][np * 2 + 1], a[mi], bhf + 2);
                    mma16816(acc[mi][np * 2 + 1], a[mi], blf + 2);
                }
            }
        }
        __syncthreads();
        if (s + 2 < nsteps) issue(s + 2, buf);
    }

    // store preactivations (fp16)
    __half* outr = g_out + (size_t)gy * PADM * 128;
    const int g = lane >> 2, t2 = (lane & 3) * 2;
#pragma unroll
    for (int mi = 0; mi < 2; mi++) {
        int row0 = mbase + m0 + mi * 16 + g;
#pragma unroll
        for (int ni = 0; ni < 8; ni++) {
            int col = n0 + ni * 8 + t2;
            *(__half2*)&outr[(size_t)row0 * 128 + col] =
                __floats2half2_rn(acc[mi][ni][0], acc[mi][ni][1]);
            *(__half2*)&outr[(size_t)(row0 + 8) * 128 + col] =
                __floats2half2_rn(acc[mi][ni][2], acc[mi][ni][3]);
        }
    }
}

// ---------------- K6: GRU epilogue -------------------------------------------------
__device__ __forceinline__ void ld8h(const __half* p, float* f) {
    uint4 v = *(const uint4*)p;
    const __half2* h = (const __half2*)&v;
#pragma unroll
    for (int j = 0; j < 4; j++) {
        float2 xy = __half22float2(h[j]);
        f[2 * j] = xy.x; f[2 * j + 1] = xy.y;
    }
}

__global__ void k_epi(const float* __restrict__ memory,
                      const float* __restrict__ b_ih,
                      const float* __restrict__ b_hh,
                      float* __restrict__ out_mem) {
    const int A = g_count;
    int i = blockIdx.x * blockDim.x + threadIdx.x;
    int m = i >> 4;
    if (m >= A) return;
    int c = (i & 15) * 8;
    int node = g_active[m];

    const size_t REG = (size_t)PADM * 128;
    const size_t off = (size_t)m * 128 + c;
    float vr[8], vz[8], vni[8], vnh[8];
    ld8h(g_out + off, vr);
    ld8h(g_out + REG + off, vz);
    ld8h(g_out + 2 * REG + off, vni);
    ld8h(g_out + 3 * REG + off, vnh);

    const float* hrow = memory + (size_t)node * D_ + c;
    float* orow = out_mem + (size_t)node * D_ + c;
    float4 h0 = *(const float4*)hrow;
    float4 h1 = *(const float4*)(hrow + 4);
    float hv[8] = {h0.x, h0.y, h0.z, h0.w, h1.x, h1.y, h1.z, h1.w};

    float res[8];
#pragma unroll
    for (int j = 0; j < 8; j++) {
        int col = c + j;
        float r = sigmoidf_(vr[j] + b_ih[col] + b_hh[col]);
        float z = sigmoidf_(vz[j] + b_ih[128 + col] + b_hh[128 + col]);
        float n = tanhf(vni[j] + b_ih[256 + col] + r * (vnh[j] + b_hh[256 + col]));
        res[j] = (1.0f - z) * n + z * hv[j];
    }
    *(float4*)orow = make_float4(res[0], res[1], res[2], res[3]);
    *(float4*)(orow + 4) = make_float4(res[4], res[5], res[6], res[7]);
}

// ---------------- launch -------------------------------------------------------------
extern "C" void kernel_launch(void* const* d_in, const int* in_sizes, int n_in,
                              void* d_out, int out_size) {
    const float* memory      = (const float*)d_in[0];
    const float* last_update = (const float*)d_in[1];
    const float* t           = (const float*)d_in[2];
    const float* feat        = (const float*)d_in[3];
    const float* time_w      = (const float*)d_in[4];
    const float* time_b      = (const float*)d_in[5];
    const float* w_ih        = (const float*)d_in[6];
    const float* w_hh        = (const float*)d_in[7];
    const float* b_ih        = (const float*)d_in[8];
    const float* b_hh        = (const float*)d_in[9];
    const int*   src         = (const int*)d_in[10];
    const int*   dst         = (const int*)d_in[11];

    float* out_mem = (float*)d_out;
    float* out_lu  = (out_size >= N_NODES * D_ + N_NODES)
                         ? out_mem + (size_t)N_NODES * D_ : nullptr;

    cudaFuncSetAttribute(k_gemm, cudaFuncAttributeMaxDynamicSharedMemorySize,
                         2 * STAGE);

    k_zero<<<(N_NODES + 255) / 256, 256>>>();
    k_scatter<<<(2 * N_EV + 255) / 256, 256>>>(src, dst, t);
    k_packw<<<384, 128>>>(w_ih, w_hh);
    k_init<<<(N_NODES * 32 + 255) / 256, 256>>>(memory, last_update, out_mem, out_lu);
    k_build<<<N_NODES, 128>>>(src, dst, t, memory, last_update, feat,
                              time_w, time_b, out_lu);
    dim3 grid((N_NODES + 127) / 128, 4);
    k_gemm<<<grid, 256, 2 * STAGE>>>();
    k_epi<<<(N_NODES * 16 + 255) / 256, 256>>>(memory, b_ih, b_hh, out_mem);
}

// round 5
// speedup vs baseline: 4.7543x; 1.3471x over previous
#include <cuda_runtime.h>
#include <cuda_fp16.h>
#include <cstdint>
#include <cstddef>

#define N_NODES 200000
#define N_EV    100000
#define D_      128
#define PADM    200064          // N_NODES rounded up to 128

// ---------------- scratch (device globals) -----------------------------------
__device__ unsigned long long g_best[N_NODES];
__device__ int                g_active[N_NODES];
__device__ int                g_count;
__device__ __align__(16) __half g_msg[(size_t)PADM * 512];     // fp16 messages
__device__ __align__(16) __half g_wh[(size_t)384 * 640];       // fp16 weights
__device__ __align__(16) __half g_out[(size_t)4 * PADM * 128]; // r|z|n_i|n_h preacts

// ---------------- helpers -----------------------------------------------------
__device__ __forceinline__ uint32_t smem_u32(const void* p) {
    uint32_t a;
    asm("{ .reg .u64 t; cvta.to.shared.u64 t, %1; cvt.u32.u64 %0, t; }"
        : "=r"(a) : "l"(p));
    return a;
}
__device__ __forceinline__ void cp16(uint32_t dst, const void* src) {
    asm volatile("cp.async.cg.shared.global [%0], [%1], 16;" :: "r"(dst), "l"(src));
}
// swizzled byte offset of (row r, byte col c) in a 128-rows x 128B tile
__device__ __forceinline__ uint32_t swz(int r, int c) {
    return (uint32_t)(r * 128 + ((((c >> 4) ^ (r & 7)) << 4) | (c & 15)));
}
__device__ __forceinline__ void ldsm4(uint32_t* r, uint32_t addr) {
    asm volatile("ldmatrix.sync.aligned.m8n8.x4.shared.b16 {%0,%1,%2,%3}, [%4];"
        : "=r"(r[0]), "=r"(r[1]), "=r"(r[2]), "=r"(r[3]) : "r"(addr));
}
__device__ __forceinline__ void mma16816(float* d, const uint32_t* a, const uint32_t* b) {
    asm volatile("mma.sync.aligned.m16n8k16.row.col.f32.f16.f16.f32 "
        "{%0,%1,%2,%3}, {%4,%5,%6,%7}, {%8,%9}, {%0,%1,%2,%3};"
        : "+f"(d[0]), "+f"(d[1]), "+f"(d[2]), "+f"(d[3])
        : "r"(a[0]), "r"(a[1]), "r"(a[2]), "r"(a[3]), "r"(b[0]), "r"(b[1]));
}

__device__ __forceinline__ float accurate_cosf(float x) {
    const float INV2PI = 0.15915493667125702f;
    const float PI2_HI = 6.28125f;
    const float PI2_LO = 1.9353071795864769e-3f;
    float k = rintf(x * INV2PI);
    float r = fmaf(-k, PI2_HI, x);
    r = fmaf(-k, PI2_LO, r);
    return cosf(r);
}
__device__ __forceinline__ float sigmoidf_(float x) { return 1.0f / (1.0f + expf(-x)); }

// ---------------- K0: zero flags ------------------------------------------------
__global__ void k_zero() {
    int i = blockIdx.x * blockDim.x + threadIdx.x;
    if (i < N_NODES) g_best[i] = 0ULL;
    if (i == 0) g_count = 0;
}

// ---------------- K2: scatter argmax --------------------------------------------
__global__ void k_scatter(const int* __restrict__ src,
                          const int* __restrict__ dst,
                          const float* __restrict__ t) {
    int i = blockIdx.x * blockDim.x + threadIdx.x;
    if (i >= 2 * N_EV) return;
    int e = (i < N_EV) ? i : i - N_EV;
    int node = (i < N_EV) ? src[e] : dst[e];
    unsigned long long key =
        (((unsigned long long)__float_as_uint(t[e])) << 32) | (unsigned)(i + 1);
    atomicMax(&g_best[node], key);
}

// ---------------- K1: defaults for inactive nodes (after scatter) ---------------
__global__ void k_init(const float* __restrict__ memory,
                       const float* __restrict__ last_update,
                       float* __restrict__ out_mem,
                       float* __restrict__ out_lu) {
    int i = blockIdx.x * blockDim.x + threadIdx.x;
    if (i < N_NODES * 32) {
        int node = i >> 5;
        if (g_best[node] == 0ULL)
            ((float4*)out_mem)[i] = ((const float4*)memory)[i];
    }
    if (i < N_NODES && out_lu && g_best[i] == 0ULL)
        out_lu[i] = last_update[i];
}

// ---------------- K3: compact + build fp16 messages (warp per node) --------------
__device__ __forceinline__ uint2 pack4h(float a, float b, float c, float d) {
    __half2 lo = __floats2half2_rn(a, b);
    __half2 hi = __floats2half2_rn(c, d);
    uint2 r;
    r.x = *(uint32_t*)&lo;
    r.y = *(uint32_t*)&hi;
    return r;
}

__global__ void k_build(const int* __restrict__ src,
                        const int* __restrict__ dst,
                        const float* __restrict__ t,
                        const float* __restrict__ memory,
                        const float* __restrict__ last_update,
                        const float* __restrict__ feat,
                        const float* __restrict__ time_w,
                        const float* __restrict__ time_b,
                        float* __restrict__ out_lu) {
    int gw = (blockIdx.x * blockDim.x + threadIdx.x) >> 5;   // node index
    if (gw >= N_NODES) return;
    unsigned long long key = g_best[gw];
    if (key == 0ULL) return;
    int lane = threadIdx.x & 31;

    int row;
    if (lane == 0) row = atomicAdd(&g_count, 1);
    row = __shfl_sync(0xffffffffu, row, 0);

    int idx = (int)(key & 0xffffffffu) - 1;
    int e = (idx < N_EV) ? idx : idx - N_EV;
    int other = (idx < N_EV) ? dst[e] : src[e];
    float tt = t[e];
    float dt = tt - last_update[gw];

    int c = lane * 4;
    float4 m0 = *(const float4*)&memory[(size_t)gw * D_ + c];
    float4 m1 = *(const float4*)&memory[(size_t)other * D_ + c];
    float4 tw = *(const float4*)&time_w[c];
    float4 tb = *(const float4*)&time_b[c];
    float4 fv = *(const float4*)&feat[(size_t)e * D_ + c];

    uint2* mrow = (uint2*)(g_msg + (size_t)row * 512);
    mrow[lane]      = pack4h(m0.x, m0.y, m0.z, m0.w);
    mrow[32 + lane] = pack4h(m1.x, m1.y, m1.z, m1.w);
    mrow[64 + lane] = pack4h(accurate_cosf(fmaf(dt, tw.x, tb.x)),
                             accurate_cosf(fmaf(dt, tw.y, tb.y)),
                             accurate_cosf(fmaf(dt, tw.z, tb.z)),
                             accurate_cosf(fmaf(dt, tw.w, tb.w)));
    mrow[96 + lane] = pack4h(fv.x, fv.y, fv.z, fv.w);

    if (lane == 0) {
        g_active[row] = gw;
        if (out_lu) out_lu[gw] = tt;
    }
}

// ---------------- K4: prepack weights (single fp16) --------------------------------
// g_wh row n (0..383): cols 0..511 = w_ih[n], cols 512..639 = w_hh[n]
__global__ void k_packw(const float* __restrict__ w_ih,
                        const float* __restrict__ w_hh) {
    int n = blockIdx.x;
    int tid = threadIdx.x;
    __half* rh = g_wh + (size_t)n * 640;
#pragma unroll
    for (int s = 0; s < 5; s++) {
        int col = s * 128 + tid;
        float w = (s < 4) ? w_ih[(size_t)n * 512 + col]
                          : w_hh[(size_t)n * 128 + tid];
        rh[col] = __float2half_rn(w);
    }
}

// ---------------- K5: fp16 mma.sync GEMM ---------------------------------------
// grid = (4, ceil(N/128)). gx: 0=r, 1=z (K=640), 2=n_i (K=512), 3=n_h (K=128).
// gy-major placement: the 4 regions of one mbase run concurrently -> A in L2.
// Step = 64 K-cols. Stage (32KB): A 16K | B 16K. Double buffered (64KB).
#define STAGE 32768

__global__ void __launch_bounds__(256, 2)
k_gemm() {
    extern __shared__ char smdyn[];
    const int A = g_count;
    const int mbase = blockIdx.y * 128;
    if (mbase >= A) return;
    const int gy = blockIdx.x;
    const int nsteps = (gy < 2) ? 10 : ((gy == 2) ? 8 : 2);
    const int wrow = (gy >= 2) ? 256 : gy * 128;

    const int tid = threadIdx.x;
    const int wid = tid >> 5, lane = tid & 31;
    const int m0 = (wid >> 1) * 32, n0 = (wid & 1) * 64;
    const uint32_t smb = smem_u32(smdyn);

    const char* b_mem = (const char*)g_wh + (size_t)wrow * 1280;
    const char* a_mem = (const char*)g_msg;

    auto issue = [&](int s, int buf) {
        // byte offsets into the 1024B A row / 1280B W row
        int ac = (gy < 2 && s >= 8) ? (s - 8) * 128 : s * 128;
        int wc = (gy == 3) ? 1024 + s * 128
                           : ((gy < 2 && s >= 8) ? 1024 + (s - 8) * 128 : s * 128);
        uint32_t st = smb + buf * STAGE;
#pragma unroll
        for (int i = 0; i < 4; i++) {
            int idx = tid + 256 * i;
            int r = idx >> 3, q = (idx & 7) * 16;
            int gr = mbase + r;
            if (gr >= A) gr = A - 1;
            cp16(st + swz(r, q), a_mem + (size_t)gr * 1024 + ac + q);
        }
#pragma unroll
        for (int i = 0; i < 4; i++) {
            int idx = tid + 256 * i;
            int r = idx >> 3, q = (idx & 7) * 16;
            cp16(st + 16384 + swz(r, q), b_mem + (size_t)r * 1280 + wc + q);
        }
        asm volatile("cp.async.commit_group;" ::: "memory");
    };

    float acc[2][8][4];
#pragma unroll
    for (int mi = 0; mi < 2; mi++)
#pragma unroll
        for (int ni = 0; ni < 8; ni++)
#pragma unroll
            for (int j = 0; j < 4; j++) acc[mi][ni][j] = 0.0f;

    issue(0, 0);
    if (nsteps > 1) issue(1, 1);

    // ldmatrix per-lane address components
    const int arow = lane & 15;
    const int acoll = (lane >> 4) << 4;
    const int browl = (lane & 7) + ((lane & 16) >> 1);
    const int bcoll = (lane & 8) << 1;

    for (int s = 0; s < nsteps; s++) {
        int buf = s & 1;
        if (s + 1 < nsteps)
            asm volatile("cp.async.wait_group 1;" ::: "memory");
        else
            asm volatile("cp.async.wait_group 0;" ::: "memory");
        __syncthreads();

        uint32_t Ast = smb + buf * STAGE;
        uint32_t Bst = Ast + 16384;

#pragma unroll
        for (int kk = 0; kk < 4; kk++) {
            int kb = kk * 32;
            uint32_t a[2][4];
            ldsm4(a[0], Ast + swz(m0 + arow, kb + acoll));
            ldsm4(a[1], Ast + swz(m0 + 16 + arow, kb + acoll));
#pragma unroll
            for (int np = 0; np < 4; np++) {
                int nb = n0 + np * 16 + browl;
                uint32_t bf[4];
                ldsm4(bf, Bst + swz(nb, kb + bcoll));
#pragma unroll
                for (int mi = 0; mi < 2; mi++) {
                    mma16816(acc[mi][np * 2],     a[mi], bf);
                    mma16816(acc[mi][np * 2 + 1], a[mi], bf + 2);
                }
            }
        }
        __syncthreads();
        if (s + 2 < nsteps) issue(s + 2, buf);
    }

    // store preactivations (fp16)
    __half* outr = g_out + (size_t)gy * PADM * 128;
    const int g = lane >> 2, t2 = (lane & 3) * 2;
#pragma unroll
    for (int mi = 0; mi < 2; mi++) {
        int row0 = mbase + m0 + mi * 16 + g;
#pragma unroll
        for (int ni = 0; ni < 8; ni++) {
            int col = n0 + ni * 8 + t2;
            *(__half2*)&outr[(size_t)row0 * 128 + col] =
                __floats2half2_rn(acc[mi][ni][0], acc[mi][ni][1]);
            *(__half2*)&outr[(size_t)(row0 + 8) * 128 + col] =
                __floats2half2_rn(acc[mi][ni][2], acc[mi][ni][3]);
        }
    }
}

// ---------------- K6: GRU epilogue -------------------------------------------------
__device__ __forceinline__ void ld8h(const __half* p, float* f) {
    uint4 v = *(const uint4*)p;
    const __half2* h = (const __half2*)&v;
#pragma unroll
    for (int j = 0; j < 4; j++) {
        float2 xy = __half22float2(h[j]);
        f[2 * j] = xy.x; f[2 * j + 1] = xy.y;
    }
}

__global__ void k_epi(const float* __restrict__ memory,
                      const float* __restrict__ b_ih,
                      const float* __restrict__ b_hh,
                      float* __restrict__ out_mem) {
    const int A = g_count;
    int i = blockIdx.x * blockDim.x + threadIdx.x;
    int m = i >> 4;
    if (m >= A) return;
    int c = (i & 15) * 8;
    int node = g_active[m];

    const size_t REG = (size_t)PADM * 128;
    const size_t off = (size_t)m * 128 + c;
    float vr[8], vz[8], vni[8], vnh[8];
    ld8h(g_out + off, vr);
    ld8h(g_out + REG + off, vz);
    ld8h(g_out + 2 * REG + off, vni);
    ld8h(g_out + 3 * REG + off, vnh);

    const float* hrow = memory + (size_t)node * D_ + c;
    float* orow = out_mem + (size_t)node * D_ + c;
    float4 h0 = *(const float4*)hrow;
    float4 h1 = *(const float4*)(hrow + 4);
    float hv[8] = {h0.x, h0.y, h0.z, h0.w, h1.x, h1.y, h1.z, h1.w};

    float res[8];
#pragma unroll
    for (int j = 0; j < 8; j++) {
        int col = c + j;
        float r = sigmoidf_(vr[j] + b_ih[col] + b_hh[col]);
        float z = sigmoidf_(vz[j] + b_ih[128 + col] + b_hh[128 + col]);
        float n = tanhf(vni[j] + b_ih[256 + col] + r * (vnh[j] + b_hh[256 + col]));
        res[j] = (1.0f - z) * n + z * hv[j];
    }
    *(float4*)orow = make_float4(res[0], res[1], res[2], res[3]);
    *(float4*)(orow + 4) = make_float4(res[4], res[5], res[6], res[7]);
}

// ---------------- launch -------------------------------------------------------------
extern "C" void kernel_launch(void* const* d_in, const int* in_sizes, int n_in,
                              void* d_out, int out_size) {
    const float* memory      = (const float*)d_in[0];
    const float* last_update = (const float*)d_in[1];
    const float* t           = (const float*)d_in[2];
    const float* feat        = (const float*)d_in[3];
    const float* time_w      = (const float*)d_in[4];
    const float* time_b      = (const float*)d_in[5];
    const float* w_ih        = (const float*)d_in[6];
    const float* w_hh        = (const float*)d_in[7];
    const float* b_ih        = (const float*)d_in[8];
    const float* b_hh        = (const float*)d_in[9];
    const int*   src         = (const int*)d_in[10];
    const int*   dst         = (const int*)d_in[11];

    float* out_mem = (float*)d_out;
    float* out_lu  = (out_size >= N_NODES * D_ + N_NODES)
                         ? out_mem + (size_t)N_NODES * D_ : nullptr;

    cudaFuncSetAttribute(k_gemm, cudaFuncAttributeMaxDynamicSharedMemorySize,
                         2 * STAGE);

    k_zero<<<(N_NODES + 255) / 256, 256>>>();
    k_scatter<<<(2 * N_EV + 255) / 256, 256>>>(src, dst, t);
    k_packw<<<384, 128>>>(w_ih, w_hh);
    k_init<<<(N_NODES * 32 + 255) / 256, 256>>>(memory, last_update, out_mem, out_lu);
    k_build<<<(N_NODES * 32 + 255) / 256, 256>>>(src, dst, t, memory, last_update,
                                                 feat, time_w, time_b, out_lu);
    dim3 grid(4, (N_NODES + 127) / 128);
    k_gemm<<<grid, 256, 2 * STAGE>>>();
    k_epi<<<(N_NODES * 16 + 255) / 256, 256>>>(memory, b_ih, b_hh, out_mem);
}